// round 1
// baseline (speedup 1.0000x reference)
#include <cuda_runtime.h>
#include <math.h>

#define B 4
#define T 2048
#define C 1024
#define H 16
#define D 64
#define BT (B*T)
#define SCALE 0.125f

// Scratch (allocation-free rule: __device__ globals)
__device__ float g_q[(size_t)BT * C];
__device__ float g_k[(size_t)BT * C];
__device__ float g_v[(size_t)BT * C];
__device__ float g_att[(size_t)BT * C];

// ---------------------------------------------------------------------------
// GEMM: out[M,N] = (X[M,K] @ W[N,K]^T + bias[N]) * scale
// 64x64 tile, BK=16, 256 threads, 4x4 per thread.
// ---------------------------------------------------------------------------
__global__ void gemm_xwT(const float* __restrict__ X, const float* __restrict__ W,
                         const float* __restrict__ bias, float* __restrict__ out,
                         int M, int N, int K, float scale) {
    __shared__ __align__(16) float As[16][64];
    __shared__ __align__(16) float Bs[16][64];
    const int tx = threadIdx.x, ty = threadIdx.y;
    const int tid = ty * 16 + tx;
    const int bm = blockIdx.y * 64, bn = blockIdx.x * 64;
    const int lrow = tid >> 2;          // 0..63
    const int lcol = (tid & 3) * 4;     // 0,4,8,12

    float acc[4][4] = {};
    const float* Ag = X + (size_t)(bm + lrow) * K + lcol;
    const float* Wg = W + (size_t)(bn + lrow) * K + lcol;

    for (int k0 = 0; k0 < K; k0 += 16) {
        float4 a = *(const float4*)(Ag + k0);
        float4 w = *(const float4*)(Wg + k0);
        As[lcol + 0][lrow] = a.x; As[lcol + 1][lrow] = a.y;
        As[lcol + 2][lrow] = a.z; As[lcol + 3][lrow] = a.w;
        Bs[lcol + 0][lrow] = w.x; Bs[lcol + 1][lrow] = w.y;
        Bs[lcol + 2][lrow] = w.z; Bs[lcol + 3][lrow] = w.w;
        __syncthreads();
#pragma unroll
        for (int kk = 0; kk < 16; kk++) {
            float4 av = *(const float4*)&As[kk][ty * 4];
            float4 bv = *(const float4*)&Bs[kk][tx * 4];
            float ar[4] = {av.x, av.y, av.z, av.w};
            float br[4] = {bv.x, bv.y, bv.z, bv.w};
#pragma unroll
            for (int r = 0; r < 4; r++)
#pragma unroll
                for (int c = 0; c < 4; c++)
                    acc[r][c] = fmaf(ar[r], br[c], acc[r][c]);
        }
        __syncthreads();
    }

    float4 bb = *(const float4*)(bias + bn + tx * 4);
    float bArr[4] = {bb.x, bb.y, bb.z, bb.w};
#pragma unroll
    for (int r = 0; r < 4; r++) {
        float4 o;
        o.x = (acc[r][0] + bArr[0]) * scale;
        o.y = (acc[r][1] + bArr[1]) * scale;
        o.z = (acc[r][2] + bArr[2]) * scale;
        o.w = (acc[r][3] + bArr[3]) * scale;
        *(float4*)(out + (size_t)(bm + ty * 4 + r) * N + bn + tx * 4) = o;
    }
}

// ---------------------------------------------------------------------------
// Scores: S[bh, i, j] = sum_d Q[b,i,h,d] * K[b,j,h,d]   (lower-triangle tiles only)
// Block = one 64x64 tile, single K-slab (D=64).
// ---------------------------------------------------------------------------
__global__ void scores_kernel(const float* __restrict__ q, const float* __restrict__ k,
                              float* __restrict__ attn) {
    const int kt = blockIdx.x, qt = blockIdx.y, bh = blockIdx.z;
    if (kt > qt) return;
    const int b = bh >> 4, h = bh & 15;

    __shared__ __align__(16) float Qs[64][64];
    __shared__ __align__(16) float Ks[64][64];
    const int tx = threadIdx.x, ty = threadIdx.y;
    const int tid = ty * 16 + tx;
    const int lrow = tid >> 2;
    const int c4 = tid & 3;

    const float* qg = q + (size_t)(b * T + qt * 64 + lrow) * C + h * 64;
    const float* kg = k + (size_t)(b * T + kt * 64 + lrow) * C + h * 64;
#pragma unroll
    for (int s = 0; s < 4; s++) {
        int col = (c4 + 4 * s) * 4;
        float4 v = *(const float4*)(qg + col);
        Qs[col + 0][lrow] = v.x; Qs[col + 1][lrow] = v.y;
        Qs[col + 2][lrow] = v.z; Qs[col + 3][lrow] = v.w;
        float4 w = *(const float4*)(kg + col);
        Ks[col + 0][lrow] = w.x; Ks[col + 1][lrow] = w.y;
        Ks[col + 2][lrow] = w.z; Ks[col + 3][lrow] = w.w;
    }
    __syncthreads();

    float acc[4][4] = {};
#pragma unroll 16
    for (int d = 0; d < 64; d++) {
        float4 qv = *(const float4*)&Qs[d][ty * 4];
        float4 kv = *(const float4*)&Ks[d][tx * 4];
        float qr[4] = {qv.x, qv.y, qv.z, qv.w};
        float kr[4] = {kv.x, kv.y, kv.z, kv.w};
#pragma unroll
        for (int r = 0; r < 4; r++)
#pragma unroll
            for (int c = 0; c < 4; c++)
                acc[r][c] = fmaf(qr[r], kr[c], acc[r][c]);
    }

    float* og = attn + (size_t)bh * T * T + (size_t)(qt * 64 + ty * 4) * T + kt * 64 + tx * 4;
#pragma unroll
    for (int r = 0; r < 4; r++) {
        float4 o = {acc[r][0], acc[r][1], acc[r][2], acc[r][3]};
        *(float4*)(og + (size_t)r * T) = o;
    }
}

// ---------------------------------------------------------------------------
// Softmax per row; causal (only j<=i valid), honors key_padding_mask,
// writes zeros for j>i (d_out is poisoned so everything must be written).
// ---------------------------------------------------------------------------
__global__ void softmax_kernel(float* __restrict__ attn, const unsigned char* __restrict__ kp) {
    const int i = blockIdx.x;
    const int bh = blockIdx.y;
    const int b = bh >> 4;
    float* row = attn + (size_t)bh * T * T + (size_t)i * T;
    const int tid = threadIdx.x;
    const int len = i + 1;

    float vals[8];
    unsigned char msk[8];
    int nk = 0;
    float m = -INFINITY;
    for (int j = tid; j < len; j += 256) {
        float s = row[j];
        unsigned char pm = kp[b * T + j];
        vals[nk] = s; msk[nk] = pm; nk++;
        if (!pm) m = fmaxf(m, s);
    }

    __shared__ float red[256];
    red[tid] = m; __syncthreads();
    for (int off = 128; off > 0; off >>= 1) {
        if (tid < off) red[tid] = fmaxf(red[tid], red[tid + off]);
        __syncthreads();
    }
    m = red[0];
    __syncthreads();

    float sum = 0.f;
    for (int t = 0; t < nk; t++) {
        float e = msk[t] ? 0.f : __expf(vals[t] - m);
        vals[t] = e;
        sum += e;
    }
    red[tid] = sum; __syncthreads();
    for (int off = 128; off > 0; off >>= 1) {
        if (tid < off) red[tid] += red[tid + off];
        __syncthreads();
    }
    float inv = 1.0f / red[0];

    int t2 = 0;
    for (int j = tid; j < len; j += 256) row[j] = vals[t2++] * inv;
    for (int j = len + tid; j < T; j += 256) row[j] = 0.f;
}

// ---------------------------------------------------------------------------
// O = P @ V per (b,h,q_tile); iterates only k-tiles <= q-tile (P upper is zero).
// Writes into g_att in [B,T,C] layout so output proj is a plain GEMM.
// ---------------------------------------------------------------------------
__global__ void av_kernel(const float* __restrict__ attn, const float* __restrict__ v,
                          float* __restrict__ out) {
    const int qt = blockIdx.x, bh = blockIdx.y;
    const int b = bh >> 4, h = bh & 15;

    __shared__ __align__(16) float Ps[64][64];
    __shared__ __align__(16) float Vs[64][64];
    const int tx = threadIdx.x, ty = threadIdx.y;
    const int tid = ty * 16 + tx;
    const int lrow = tid >> 2;
    const int c4 = tid & 3;

    float acc[4][4] = {};
    for (int kt = 0; kt <= qt; kt++) {
        const float* pg = attn + (size_t)bh * T * T + (size_t)(qt * 64 + lrow) * T + kt * 64;
        const float* vg = v + (size_t)(b * T + kt * 64 + lrow) * C + h * 64;
#pragma unroll
        for (int s = 0; s < 4; s++) {
            int col = (c4 + 4 * s) * 4;
            float4 p = *(const float4*)(pg + col);
            Ps[col + 0][lrow] = p.x; Ps[col + 1][lrow] = p.y;
            Ps[col + 2][lrow] = p.z; Ps[col + 3][lrow] = p.w;
            *(float4*)&Vs[lrow][col] = *(const float4*)(vg + col);
        }
        __syncthreads();
#pragma unroll 16
        for (int kk = 0; kk < 64; kk++) {
            float4 pv = *(const float4*)&Ps[kk][ty * 4];
            float4 vv = *(const float4*)&Vs[kk][tx * 4];
            float pr[4] = {pv.x, pv.y, pv.z, pv.w};
            float vr[4] = {vv.x, vv.y, vv.z, vv.w};
#pragma unroll
            for (int r = 0; r < 4; r++)
#pragma unroll
                for (int c = 0; c < 4; c++)
                    acc[r][c] = fmaf(pr[r], vr[c], acc[r][c]);
        }
        __syncthreads();
    }

#pragma unroll
    for (int r = 0; r < 4; r++) {
        float4 o = {acc[r][0], acc[r][1], acc[r][2], acc[r][3]};
        *(float4*)(out + (size_t)(b * T + qt * 64 + ty * 4 + r) * C + h * 64 + tx * 4) = o;
    }
}

// ---------------------------------------------------------------------------
extern "C" void kernel_launch(void* const* d_in, const int* in_sizes, int n_in,
                              void* d_out, int out_size) {
    const float* query = (const float*)d_in[0];
    const float* key   = (const float*)d_in[1];
    const float* value = (const float*)d_in[2];
    // d_in[3] = attn_mask (causal triu, hardcoded)
    const unsigned char* kp = (const unsigned char*)d_in[4];
    const float* Wq = (const float*)d_in[5];  const float* bq = (const float*)d_in[6];
    const float* Wk = (const float*)d_in[7];  const float* bk = (const float*)d_in[8];
    const float* Wv = (const float*)d_in[9];  const float* bv = (const float*)d_in[10];
    const float* Wo = (const float*)d_in[11]; const float* bo = (const float*)d_in[12];

    float* y    = (float*)d_out;
    float* attn = y + (size_t)BT * C;  // tuple order: (y, attn_weights)

    float *gq, *gk, *gv, *gatt;
    cudaGetSymbolAddress((void**)&gq, g_q);
    cudaGetSymbolAddress((void**)&gk, g_k);
    cudaGetSymbolAddress((void**)&gv, g_v);
    cudaGetSymbolAddress((void**)&gatt, g_att);

    dim3 gblk(16, 16);
    dim3 ggrid(C / 64, BT / 64);  // (16, 128)

    // Q/K/V projections (SCALE folded into Q)
    gemm_xwT<<<ggrid, gblk>>>(query, Wq, bq, gq, BT, C, C, SCALE);
    gemm_xwT<<<ggrid, gblk>>>(key,   Wk, bk, gk, BT, C, C, 1.0f);
    gemm_xwT<<<ggrid, gblk>>>(value, Wv, bv, gv, BT, C, C, 1.0f);

    // Scores (lower triangle tiles only)
    dim3 sgrid(T / 64, T / 64, B * H);  // (32, 32, 64)
    scores_kernel<<<sgrid, gblk>>>(gq, gk, attn);

    // Row softmax + zero-fill masked region
    dim3 smgrid(T, B * H);  // (2048, 64)
    softmax_kernel<<<smgrid, 256>>>(attn, kp);

    // P @ V
    dim3 avgrid(T / 64, B * H);  // (32, 64)
    av_kernel<<<avgrid, gblk>>>(attn, gv, gatt);

    // Output projection
    gemm_xwT<<<ggrid, gblk>>>(gatt, Wo, bo, y, BT, C, C, 1.0f);
}

// round 2
// speedup vs baseline: 1.2810x; 1.2810x over previous
#include <cuda_runtime.h>
#include <math.h>

#define B 4
#define T 2048
#define C 1024
#define H 16
#define D 64
#define BT (B*T)
#define SCALE 0.125f

// Scratch (allocation-free rule: __device__ globals)
__device__ float g_q[(size_t)BT * C];
__device__ float g_k[(size_t)BT * C];
__device__ float g_v[(size_t)BT * C];
__device__ float g_att[(size_t)BT * C];

// ---------------------------------------------------------------------------
// GEMM: out[M,N] = (X[M,K] @ W[N,K]^T + bias[N]) * scale
// 128x128 tile, BK=8, 256 threads, 8x8 per thread, double-buffered smem.
// ---------------------------------------------------------------------------
__global__ __launch_bounds__(256, 2)
void gemm128(const float* __restrict__ X, const float* __restrict__ W,
             const float* __restrict__ bias, float* __restrict__ out,
             int M, int N, int K, float scale) {
    __shared__ __align__(16) float As[2][8][132];
    __shared__ __align__(16) float Bs[2][8][132];
    const int tid = threadIdx.x;
    const int tx = tid & 15, ty = tid >> 4;
    const int bm = blockIdx.y * 128, bn = blockIdx.x * 128;
    const int lr = tid >> 1;          // 0..127
    const int lk = (tid & 1) * 4;     // 0 or 4

    const float* Xg = X + (size_t)(bm + lr) * K + lk;
    const float* Wg = W + (size_t)(bn + lr) * K + lk;

    float acc[8][8] = {};

    float4 xa = *(const float4*)Xg;
    float4 wb = *(const float4*)Wg;
    As[0][lk+0][lr]=xa.x; As[0][lk+1][lr]=xa.y; As[0][lk+2][lr]=xa.z; As[0][lk+3][lr]=xa.w;
    Bs[0][lk+0][lr]=wb.x; Bs[0][lk+1][lr]=wb.y; Bs[0][lk+2][lr]=wb.z; Bs[0][lk+3][lr]=wb.w;
    __syncthreads();

    int buf = 0;
    for (int k0 = 8; k0 <= K; k0 += 8) {
        if (k0 < K) {
            xa = *(const float4*)(Xg + k0);
            wb = *(const float4*)(Wg + k0);
        }
#pragma unroll
        for (int kk = 0; kk < 8; kk++) {
            float4 a0 = *(const float4*)&As[buf][kk][ty*4];
            float4 a1 = *(const float4*)&As[buf][kk][ty*4+64];
            float4 b0 = *(const float4*)&Bs[buf][kk][tx*4];
            float4 b1 = *(const float4*)&Bs[buf][kk][tx*4+64];
            float ar[8] = {a0.x,a0.y,a0.z,a0.w,a1.x,a1.y,a1.z,a1.w};
            float br[8] = {b0.x,b0.y,b0.z,b0.w,b1.x,b1.y,b1.z,b1.w};
#pragma unroll
            for (int r = 0; r < 8; r++)
#pragma unroll
                for (int c = 0; c < 8; c++)
                    acc[r][c] = fmaf(ar[r], br[c], acc[r][c]);
        }
        if (k0 < K) {
            int nb = buf ^ 1;
            As[nb][lk+0][lr]=xa.x; As[nb][lk+1][lr]=xa.y; As[nb][lk+2][lr]=xa.z; As[nb][lk+3][lr]=xa.w;
            Bs[nb][lk+0][lr]=wb.x; Bs[nb][lk+1][lr]=wb.y; Bs[nb][lk+2][lr]=wb.z; Bs[nb][lk+3][lr]=wb.w;
        }
        __syncthreads();
        buf ^= 1;
    }

    float4 bb0 = *(const float4*)(bias + bn + tx*4);
    float4 bb1 = *(const float4*)(bias + bn + 64 + tx*4);
    float bl[8] = {bb0.x,bb0.y,bb0.z,bb0.w,bb1.x,bb1.y,bb1.z,bb1.w};
#pragma unroll
    for (int r = 0; r < 8; r++) {
        int row = bm + ((r < 4) ? (ty*4 + r) : (64 + ty*4 + r - 4));
        float4 o0, o1;
        o0.x=(acc[r][0]+bl[0])*scale; o0.y=(acc[r][1]+bl[1])*scale;
        o0.z=(acc[r][2]+bl[2])*scale; o0.w=(acc[r][3]+bl[3])*scale;
        o1.x=(acc[r][4]+bl[4])*scale; o1.y=(acc[r][5]+bl[5])*scale;
        o1.z=(acc[r][6]+bl[6])*scale; o1.w=(acc[r][7]+bl[7])*scale;
        *(float4*)(out + (size_t)row * N + bn + tx*4)      = o0;
        *(float4*)(out + (size_t)row * N + bn + 64 + tx*4) = o1;
    }
}

// ---------------------------------------------------------------------------
// Scores: S[bh,i,j] = Q[b,i,h,:] . K[b,j,h,:]  (lower-triangle 128x128 tiles)
// ---------------------------------------------------------------------------
__global__ __launch_bounds__(256, 2)
void scores128(const float* __restrict__ q, const float* __restrict__ k,
               float* __restrict__ attn) {
    const int kt = blockIdx.x, qt = blockIdx.y, bh = blockIdx.z;
    if (kt > qt) return;
    const int b = bh >> 4, h = bh & 15;

    __shared__ __align__(16) float Qs[2][8][132];
    __shared__ __align__(16) float Ks[2][8][132];
    const int tid = threadIdx.x;
    const int tx = tid & 15, ty = tid >> 4;
    const int lr = tid >> 1;
    const int lk = (tid & 1) * 4;

    const float* Xg = q + (size_t)(b*T + qt*128 + lr) * C + h*64 + lk;
    const float* Wg = k + (size_t)(b*T + kt*128 + lr) * C + h*64 + lk;

    float acc[8][8] = {};

    float4 xa = *(const float4*)Xg;
    float4 wb = *(const float4*)Wg;
    Qs[0][lk+0][lr]=xa.x; Qs[0][lk+1][lr]=xa.y; Qs[0][lk+2][lr]=xa.z; Qs[0][lk+3][lr]=xa.w;
    Ks[0][lk+0][lr]=wb.x; Ks[0][lk+1][lr]=wb.y; Ks[0][lk+2][lr]=wb.z; Ks[0][lk+3][lr]=wb.w;
    __syncthreads();

    int buf = 0;
    for (int k0 = 8; k0 <= 64; k0 += 8) {
        if (k0 < 64) {
            xa = *(const float4*)(Xg + k0);
            wb = *(const float4*)(Wg + k0);
        }
#pragma unroll
        for (int kk = 0; kk < 8; kk++) {
            float4 a0 = *(const float4*)&Qs[buf][kk][ty*4];
            float4 a1 = *(const float4*)&Qs[buf][kk][ty*4+64];
            float4 b0 = *(const float4*)&Ks[buf][kk][tx*4];
            float4 b1 = *(const float4*)&Ks[buf][kk][tx*4+64];
            float ar[8] = {a0.x,a0.y,a0.z,a0.w,a1.x,a1.y,a1.z,a1.w};
            float br[8] = {b0.x,b0.y,b0.z,b0.w,b1.x,b1.y,b1.z,b1.w};
#pragma unroll
            for (int r = 0; r < 8; r++)
#pragma unroll
                for (int c = 0; c < 8; c++)
                    acc[r][c] = fmaf(ar[r], br[c], acc[r][c]);
        }
        if (k0 < 64) {
            int nb = buf ^ 1;
            Qs[nb][lk+0][lr]=xa.x; Qs[nb][lk+1][lr]=xa.y; Qs[nb][lk+2][lr]=xa.z; Qs[nb][lk+3][lr]=xa.w;
            Ks[nb][lk+0][lr]=wb.x; Ks[nb][lk+1][lr]=wb.y; Ks[nb][lk+2][lr]=wb.z; Ks[nb][lk+3][lr]=wb.w;
        }
        __syncthreads();
        buf ^= 1;
    }

    float* og = attn + (size_t)bh * T * T + (size_t)(qt*128) * T + kt*128;
#pragma unroll
    for (int r = 0; r < 8; r++) {
        int row = (r < 4) ? (ty*4 + r) : (64 + ty*4 + r - 4);
        float4 o0 = {acc[r][0], acc[r][1], acc[r][2], acc[r][3]};
        float4 o1 = {acc[r][4], acc[r][5], acc[r][6], acc[r][7]};
        *(float4*)(og + (size_t)row * T + tx*4)      = o0;
        *(float4*)(og + (size_t)row * T + 64 + tx*4) = o1;
    }
}

// ---------------------------------------------------------------------------
// Softmax per row; causal, honors key_padding_mask, zero-fills j>i.
// ---------------------------------------------------------------------------
__global__ void softmax_kernel(float* __restrict__ attn, const unsigned char* __restrict__ kp) {
    const int i = blockIdx.x;
    const int bh = blockIdx.y;
    const int b = bh >> 4;
    float* row = attn + (size_t)bh * T * T + (size_t)i * T;
    const int tid = threadIdx.x;
    const int len = i + 1;

    float vals[8];
    unsigned char msk[8];
    int nk = 0;
    float m = -INFINITY;
    for (int j = tid; j < len; j += 256) {
        float s = row[j];
        unsigned char pm = kp[b * T + j];
        vals[nk] = s; msk[nk] = pm; nk++;
        if (!pm) m = fmaxf(m, s);
    }

    __shared__ float red[256];
    red[tid] = m; __syncthreads();
    for (int off = 128; off > 0; off >>= 1) {
        if (tid < off) red[tid] = fmaxf(red[tid], red[tid + off]);
        __syncthreads();
    }
    m = red[0];
    __syncthreads();

    float sum = 0.f;
    for (int t = 0; t < nk; t++) {
        float e = msk[t] ? 0.f : __expf(vals[t] - m);
        vals[t] = e;
        sum += e;
    }
    red[tid] = sum; __syncthreads();
    for (int off = 128; off > 0; off >>= 1) {
        if (tid < off) red[tid] += red[tid + off];
        __syncthreads();
    }
    float inv = 1.0f / red[0];

    int t2 = 0;
    for (int j = tid; j < len; j += 256) row[j] = vals[t2++] * inv;
    for (int j = len + tid; j < T; j += 256) row[j] = 0.f;
}

// ---------------------------------------------------------------------------
// O = P @ V per (b,h,q128tile). 128x64 out tile, 8x4 per thread, k-slabs of 64.
// ---------------------------------------------------------------------------
__global__ __launch_bounds__(256)
void av128(const float* __restrict__ attn, const float* __restrict__ v,
           float* __restrict__ out) {
    const int qt = blockIdx.x, bh = blockIdx.y;
    const int b = bh >> 4, h = bh & 15;

    __shared__ __align__(16) float Ps[64][132];   // [k][m]
    __shared__ __align__(16) float Vs[64][68];    // [k][n]
    const int tid = threadIdx.x;
    const int tx = tid & 15, ty = tid >> 4;
    const int pr = tid >> 1;            // 0..127 (P row)
    const int pc0 = (tid & 1) * 4;      // 0 or 4

    float acc[8][4] = {};
    const int nkt = 2 * qt + 2;         // 64-wide key tiles covering causal span

    for (int kt = 0; kt < nkt; kt++) {
        const float* pg = attn + (size_t)bh * T * T + (size_t)(qt*128 + pr) * T + kt*64;
#pragma unroll
        for (int i = 0; i < 8; i++) {
            int col = pc0 + i * 8;
            float4 p = *(const float4*)(pg + col);
            Ps[col+0][pr] = p.x; Ps[col+1][pr] = p.y;
            Ps[col+2][pr] = p.z; Ps[col+3][pr] = p.w;
        }
#pragma unroll
        for (int i = 0; i < 4; i++) {
            int idx = tid + i * 256;
            int vr = idx >> 4;
            int vc = (idx & 15) * 4;
            *(float4*)&Vs[vr][vc] =
                *(const float4*)(v + (size_t)(b*T + kt*64 + vr) * C + h*64 + vc);
        }
        __syncthreads();

#pragma unroll 8
        for (int kk = 0; kk < 64; kk++) {
            float4 p0 = *(const float4*)&Ps[kk][ty*4];
            float4 p1 = *(const float4*)&Ps[kk][ty*4+64];
            float4 vv = *(const float4*)&Vs[kk][tx*4];
            float pr8[8] = {p0.x,p0.y,p0.z,p0.w,p1.x,p1.y,p1.z,p1.w};
            float vr4[4] = {vv.x,vv.y,vv.z,vv.w};
#pragma unroll
            for (int r = 0; r < 8; r++)
#pragma unroll
                for (int c = 0; c < 4; c++)
                    acc[r][c] = fmaf(pr8[r], vr4[c], acc[r][c]);
        }
        __syncthreads();
    }

#pragma unroll
    for (int r = 0; r < 8; r++) {
        int row = (r < 4) ? (ty*4 + r) : (64 + ty*4 + r - 4);
        float4 o = {acc[r][0], acc[r][1], acc[r][2], acc[r][3]};
        *(float4*)(out + (size_t)(b*T + qt*128 + row) * C + h*64 + tx*4) = o;
    }
}

// ---------------------------------------------------------------------------
extern "C" void kernel_launch(void* const* d_in, const int* in_sizes, int n_in,
                              void* d_out, int out_size) {
    const float* query = (const float*)d_in[0];
    const float* key   = (const float*)d_in[1];
    const float* value = (const float*)d_in[2];
    // d_in[3] = attn_mask (causal triu, hardcoded)
    const unsigned char* kp = (const unsigned char*)d_in[4];
    const float* Wq = (const float*)d_in[5];  const float* bq = (const float*)d_in[6];
    const float* Wk = (const float*)d_in[7];  const float* bk = (const float*)d_in[8];
    const float* Wv = (const float*)d_in[9];  const float* bv = (const float*)d_in[10];
    const float* Wo = (const float*)d_in[11]; const float* bo = (const float*)d_in[12];

    float* y    = (float*)d_out;
    float* attn = y + (size_t)BT * C;  // tuple order: (y, attn_weights)

    float *gq, *gk, *gv, *gatt;
    cudaGetSymbolAddress((void**)&gq, g_q);
    cudaGetSymbolAddress((void**)&gk, g_k);
    cudaGetSymbolAddress((void**)&gv, g_v);
    cudaGetSymbolAddress((void**)&gatt, g_att);

    dim3 ggrid(C / 128, BT / 128);  // (8, 64)

    // Q/K/V projections (SCALE folded into Q)
    gemm128<<<ggrid, 256>>>(query, Wq, bq, gq, BT, C, C, SCALE);
    gemm128<<<ggrid, 256>>>(key,   Wk, bk, gk, BT, C, C, 1.0f);
    gemm128<<<ggrid, 256>>>(value, Wv, bv, gv, BT, C, C, 1.0f);

    // Scores (lower-triangle 128x128 tiles)
    dim3 sgrid(T / 128, T / 128, B * H);  // (16, 16, 64)
    scores128<<<sgrid, 256>>>(gq, gk, attn);

    // Row softmax + zero-fill masked region
    dim3 smgrid(T, B * H);
    softmax_kernel<<<smgrid, 256>>>(attn, kp);

    // P @ V
    dim3 avgrid(T / 128, B * H);  // (16, 64)
    av128<<<avgrid, 256>>>(attn, gv, gatt);

    // Output projection
    gemm128<<<ggrid, 256>>>(gatt, Wo, bo, y, BT, C, C, 1.0f);
}